// round 17
// baseline (speedup 1.0000x reference)
#include <cuda_runtime.h>
#include <cuda_fp16.h>
#include <cstdint>

#define NTOK    65536
#define VOCAB   50257
#define VOCABP  50304                 // 393 * 128
#define NVT     (VOCABP / 128)        // 393 tiles
#define THREADS 256

// ---------------- scratch (device globals: allocation-free) ----------------
__device__ __half g_Hv[(size_t)VOCABP * 512];    // activations (in-place per phase)
__device__ __half g_Rh[(size_t)VOCABP * 512];    // final table (f16)
__device__ __half g_W0h[2048 * 512];
__device__ __half g_W1h[2048 * 512];
__device__ __half g_Wlh[512 * 512];
__device__ int    g_used[VOCABP];
__device__ int    g_slot[VOCABP];
__device__ int    g_uid[VOCABP];
__device__ int    g_nuniq;

// ---------------- helpers ----------------
__device__ __forceinline__ uint32_t smem_u32(const void* p) {
    uint32_t a;
    asm("{ .reg .u64 t; cvta.to.shared.u64 t, %1; cvt.u32.u64 %0, t; }"
        : "=r"(a) : "l"(p));
    return a;
}
__device__ __forceinline__ void cp16(uint32_t dst, const void* src) {
    asm volatile("cp.async.cg.shared.global [%0], [%1], 16;"
                 :: "r"(dst), "l"(src));
}
__device__ __forceinline__ uint4 ldsm_x4(uint32_t a) {
    uint4 v;
    asm volatile("ldmatrix.sync.aligned.m8n8.x4.shared.b16 {%0,%1,%2,%3}, [%4];"
                 : "=r"(v.x), "=r"(v.y), "=r"(v.z), "=r"(v.w) : "r"(a));
    return v;
}
__device__ __forceinline__ void mma_f16(float c[4], const uint4& a,
                                        uint32_t b0, uint32_t b1) {
    asm volatile(
        "mma.sync.aligned.m16n8k16.row.col.f32.f16.f16.f32 "
        "{%0,%1,%2,%3}, {%4,%5,%6,%7}, {%8,%9}, {%0,%1,%2,%3};"
        : "+f"(c[0]), "+f"(c[1]), "+f"(c[2]), "+f"(c[3])
        : "r"(a.x), "r"(a.y), "r"(a.z), "r"(a.w), "r"(b0), "r"(b1));
}
__device__ __forceinline__ __half2 h2tanh_a(__half2 x) {
    uint32_t y, xi = *(uint32_t*)&x;
    asm("tanh.approx.f16x2 %0, %1;" : "=r"(y) : "r"(xi));
    return *(__half2*)&y;
}

// ---------------- dedup pipeline ----------------
__global__ void __launch_bounds__(256) mark_k(const int* __restrict__ ids) {
    int t = blockIdx.x * 256 + threadIdx.x;
    if (t < NTOK) g_used[ids[t]] = 1;
}
__global__ void __launch_bounds__(256) compact_k() {
    int i = blockIdx.x * 256 + threadIdx.x;
    int used = (i < VOCABP) ? g_used[i] : 0;
    unsigned bal = __ballot_sync(0xffffffffu, used);
    int lane = threadIdx.x & 31, warp = threadIdx.x >> 5;
    __shared__ int wbase[8];
    __shared__ int bbase;
    if (lane == 0) wbase[warp] = __popc(bal);
    __syncthreads();
    if (threadIdx.x == 0) {
        int s = 0;
        #pragma unroll
        for (int w = 0; w < 8; ++w) { int c = wbase[w]; wbase[w] = s; s += c; }
        bbase = atomicAdd(&g_nuniq, s);
    }
    __syncthreads();
    if (used) {
        int rank = bbase + wbase[warp] + __popc(bal & ((1u << lane) - 1));
        g_slot[i] = rank;
        g_uid[rank] = i;
    }
}

// ---------------- prep: weights -> f16 + dedup reset, one launch ----------------
__global__ void __launch_bounds__(256) f2h_all(const float* __restrict__ W0,
                                               const float* __restrict__ W1,
                                               const float* __restrict__ Wl) {
    int i = blockIdx.x * 256 + threadIdx.x;
    if (i < VOCABP) g_used[i] = 0;
    if (i == 0) g_nuniq = 0;
    if (i >= 589824) return;
    const float* src; __half* dst; int off;
    if (i < 262144)      { src = W0; dst = g_W0h; off = i; }
    else if (i < 524288) { src = W1; dst = g_W1h; off = i - 262144; }
    else                 { src = Wl; dst = g_Wlh; off = i - 524288; }
    float4 v = ((const float4*)src)[off];
    __half2 a = __floats2half2_rn(v.x, v.y);
    __half2 b = __floats2half2_rn(v.z, v.w);
    uint2 u;
    u.x = *(uint32_t*)&a; u.y = *(uint32_t*)&b;
    *(uint2*)(dst + (size_t)off * 4) = u;
}

// ---------------- compacted emb gather -> f16 table ----------------
__global__ void __launch_bounds__(256) emb_gather(const float* __restrict__ emb) {
    size_t i = (size_t)blockIdx.x * 256 + threadIdx.x;   // VOCABP*64 threads
    int row = (int)(i >> 6);
    const int nu = g_nuniq;
    const int lim = (nu + 127) & ~127;
    if (row >= lim) return;                   // never read — skip write
    int c = (int)(i & 63) * 8;
    uint4 u = make_uint4(0, 0, 0, 0);
    if (row < nu) {
        int id = g_uid[row];
        const float4* p = (const float4*)(emb + (size_t)id * 512 + c);
        float4 v0 = p[0], v1 = p[1];
        __half2 h0 = __floats2half2_rn(v0.x, v0.y);
        __half2 h1 = __floats2half2_rn(v0.z, v0.w);
        __half2 h2 = __floats2half2_rn(v1.x, v1.y);
        __half2 h3 = __floats2half2_rn(v1.z, v1.w);
        u.x = *(uint32_t*)&h0; u.y = *(uint32_t*)&h1;
        u.z = *(uint32_t*)&h2; u.w = *(uint32_t*)&h3;
    }
    *(uint4*)(g_Hv + i * 8) = u;
}

// ======= fused layer0 -> layer1 -> final, 128-row tile (R8 structure, verbatim) ====
// smem: A resident 128 x 1040B; B 3 stages x up to 192 x 80B; bias 3x512 f32
#define LA_STRIDE 1040
#define L_AOFF    0
#define L_BOFF    (128 * LA_STRIDE)            // 133120
#define L_BSTAGE  (192 * 80)                   // 15360 (layer); fin uses 128*80
#define F_BSTAGE  (128 * 80)                   // 10240
#define L_BIASOFF (L_BOFF + 3 * L_BSTAGE)      // 179200
#define L_SMEM    (L_BIASOFF + 3 * 512 * 4)    // 185344

__global__ void __launch_bounds__(THREADS, 1) fused_gemm(
    const float* __restrict__ bih0, const float* __restrict__ bhh0,
    const float* __restrict__ bih1, const float* __restrict__ bhh1,
    const float* __restrict__ blin)
{
    const size_t tok0 = (size_t)blockIdx.x * 128;
    if ((int)tok0 >= g_nuniq) return;

    extern __shared__ char smem[];
    const int tid  = threadIdx.x;
    const int lane = tid & 31, wid = tid >> 5;
    const int mw = wid >> 2, nw = wid & 3;      // 2 M-warps x 4 N-warps
    const uint32_t sb = smem_u32(smem);
    float* bias_s = (float*)(smem + L_BIASOFF);

    __half* Arows = g_Hv + tok0 * 512;          // this tile's activation rows

    // per-lane ldmatrix base addresses (A layout identical in all phases)
    const int within = lane & 7, grp = lane >> 3;
    uint32_t aBase[4];
    #pragma unroll
    for (int mi = 0; mi < 4; ++mi) {
        int m = mw * 64 + mi * 16 + within + 8 * (grp & 1);
        aBase[mi] = sb + L_AOFF + (uint32_t)m * LA_STRIDE + (grp >> 1) * 16;
    }
    uint32_t bBaseL[3];                         // layer phases: 3 gates x 16n
    #pragma unroll
    for (int g = 0; g < 3; ++g) {
        int n = g * 64 + nw * 16 + within + 8 * (grp >> 1);
        bBaseL[g] = (uint32_t)n * 80 + (grp & 1) * 16;
    }
    uint32_t bBaseF[2];                         // fin phase: 2 x 16n
    #pragma unroll
    for (int t = 0; t < 2; ++t) {
        int n = nw * 32 + t * 16 + within + 8 * (grp >> 1);
        bBaseF[t] = (uint32_t)n * 80 + (grp & 1) * 16;
    }

    // A resident load (32 x 16B per thread), committed with caller's B stage0
    auto loadA = [&]() {
        #pragma unroll
        for (int j = 0; j < 32; ++j) {
            int idx = tid + 256 * j;
            int r = idx >> 6, c16 = idx & 63;
            cp16(sb + L_AOFF + (uint32_t)r * LA_STRIDE + c16 * 16,
                 Arows + (size_t)r * 512 + c16 * 8);
        }
    };

    // ================= LSTM phases =================
    for (int L = 0; L < 2; ++L) {
        const __half* Wh   = L ? g_W1h : g_W0h;
        const float*  b_ih = L ? bih1 : bih0;
        const float*  b_hh = L ? bhh1 : bhh0;

        if (L) { __threadfence_block(); }       // own h STGs -> visible to own cp.async
        __syncthreads();                        // prev-phase smem reads done

        for (int j = tid; j < 512; j += THREADS) {
            bias_s[j]        = b_ih[j]        + b_hh[j];          // i
            bias_s[512 + j]  = b_ih[1024 + j] + b_hh[1024 + j];   // g
            bias_s[1024 + j] = b_ih[1536 + j] + b_hh[1536 + j];   // o
        }

        auto stage_copyB = [&](int stage, int ncc, int kc) {
            const uint32_t b_s = sb + L_BOFF + stage * L_BSTAGE;
            #pragma unroll
            for (int j = 0; j < 3; ++j) {
                int idx = tid + 256 * j;
                int n = idx >> 2, c8 = idx & 3;
                int gate = n >> 6, nn = n & 63;
                int grow = (gate + (gate > 0)) * 512 + ncc * 64 + nn; // skip f
                cp16(b_s + (uint32_t)n * 80 + c8 * 16,
                     Wh + (size_t)grow * 512 + kc * 32 + c8 * 8);
            }
            asm volatile("cp.async.commit_group;" ::: "memory");
        };

        loadA();
        stage_copyB(0, 0, 0);
        stage_copyB(1, 0, 1);

        float acc[3][4][2][4];

        for (int nc = 0; nc < 8; ++nc) {
            #pragma unroll
            for (int g = 0; g < 3; ++g)
                #pragma unroll
                for (int mi = 0; mi < 4; ++mi)
                    #pragma unroll
                    for (int ni = 0; ni < 2; ++ni)
                        #pragma unroll
                        for (int q = 0; q < 4; ++q) acc[g][mi][ni][q] = 0.0f;

            for (int kc = 0; kc < 16; ++kc) {
                if (kc < 15) asm volatile("cp.async.wait_group 1;" ::: "memory");
                else         asm volatile("cp.async.wait_group 0;" ::: "memory");
                __syncthreads();

                const uint32_t b_s = sb + L_BOFF + (kc % 3) * L_BSTAGE;

                uint4 af[4][2];
                #pragma unroll
                for (int mi = 0; mi < 4; ++mi)
                    #pragma unroll
                    for (int ks = 0; ks < 2; ++ks)
                        af[mi][ks] = ldsm_x4(aBase[mi] + (kc * 32 + ks * 16) * 2);

                #pragma unroll
                for (int g = 0; g < 3; ++g) {
                    #pragma unroll
                    for (int ks = 0; ks < 2; ++ks) {
                        uint4 bv = ldsm_x4(b_s + bBaseL[g] + ks * 32);
                        #pragma unroll
                        for (int mi = 0; mi < 4; ++mi) {
                            mma_f16(acc[g][mi][0], af[mi][ks], bv.x, bv.y);
                            mma_f16(acc[g][mi][1], af[mi][ks], bv.z, bv.w);
                        }
                    }
                }
                if (kc < 14) stage_copyB((kc + 2) % 3, nc, kc + 2);
            }
            __syncthreads();
            if (nc < 7) { stage_copyB(0, nc + 1, 0); stage_copyB(1, nc + 1, 1); }

            // epilogue: h = sig(o)*tanh( sig(i)*tanh(g) ), f16x2 tanh (2 elems/MUFU)
            const __half2 half05 = __floats2half2_rn(0.5f, 0.5f);
            #pragma unroll
            for (int mi = 0; mi < 4; ++mi) {
                #pragma unroll
                for (int ni = 0; ni < 2; ++ni) {
                    const int col = nc * 64 + nw * 16 + ni * 8 + 2 * (lane & 3);
                    const float bi0 = bias_s[col],        bi1 = bias_s[col + 1];
                    const float bg0 = bias_s[512 + col],  bg1 = bias_s[512 + col + 1];
                    const float bo0 = bias_s[1024 + col], bo1 = bias_s[1024 + col + 1];
                    #pragma unroll
                    for (int e = 0; e < 2; ++e) {
                        const int row = mw * 64 + mi * 16 + e * 8 + (lane >> 2);
                        float iv0 = acc[0][mi][ni][2 * e + 0] + bi0;
                        float iv1 = acc[0][mi][ni][2 * e + 1] + bi1;
                        float gv0 = acc[1][mi][ni][2 * e + 0] + bg0;
                        float gv1 = acc[1][mi][ni][2 * e + 1] + bg1;
                        float ov0 = acc[2][mi][ni][2 * e + 0] + bo0;
                        float ov1 = acc[2][mi][ni][2 * e + 1] + bo1;
                        __half2 si = __hfma2(h2tanh_a(__floats2half2_rn(0.5f * iv0,
                                                                        0.5f * iv1)),
                                             half05, half05);
                        __half2 tg = h2tanh_a(__floats2half2_rn(gv0, gv1));
                        __half2 cc = __hmul2(si, tg);
                        __half2 so = __hfma2(h2tanh_a(__floats2half2_rn(0.5f * ov0,
                                                                        0.5f * ov1)),
                                             half05, half05);
                        __half2 hh = __hmul2(so, h2tanh_a(cc));
                        *(__half2*)(Arows + (size_t)row * 512 + col) = hh;
                    }
                }
            }
        }
    }

    // ================= final linear phase =================
    __threadfence_block();
    __syncthreads();
    for (int j = tid; j < 512; j += THREADS) bias_s[j] = blin[j];

    auto stage_copyF = [&](int stage, int ncc, int kc) {
        const uint32_t b_s = sb + L_BOFF + stage * F_BSTAGE;
        #pragma unroll
        for (int j = 0; j < 2; ++j) {
            int idx = tid + 256 * j;
            int n = idx >> 2, c8 = idx & 3;
            int grow = ncc * 128 + n;
            cp16(b_s + (uint32_t)n * 80 + c8 * 16,
                 g_Wlh + (size_t)grow * 512 + kc * 32 + c8 * 8);
        }
        asm volatile("cp.async.commit_group;" ::: "memory");
    };

    loadA();
    stage_copyF(0, 0, 0);
    stage_copyF(1, 0, 1);

    float facc[4][4][4];

    for (int nc = 0; nc < 4; ++nc) {
        #pragma unroll
        for (int mi = 0; mi < 4; ++mi)
            #pragma unroll
            for (int ni = 0; ni < 4; ++ni)
                #pragma unroll
                for (int q = 0; q < 4; ++q) facc[mi][ni][q] = 0.0f;

        for (int kc = 0; kc < 16; ++kc) {
            if (kc < 15) asm volatile("cp.async.wait_group 1;" ::: "memory");
            else         asm volatile("cp.async.wait_group 0;" ::: "memory");
            __syncthreads();

            const uint32_t b_s = sb + L_BOFF + (kc % 3) * F_BSTAGE;

            uint4 af[4][2];
            #pragma unroll
            for (int mi = 0; mi < 4; ++mi)
                #pragma unroll
                for (int ks = 0; ks < 2; ++ks)
                    af[mi][ks] = ldsm_x4(aBase[mi] + (kc * 32 + ks * 16) * 2);

            #pragma unroll
            for (int t = 0; t < 2; ++t) {
                #pragma unroll
                for (int ks = 0; ks < 2; ++ks) {
                    uint4 bv = ldsm_x4(b_s + bBaseF[t] + ks * 32);
                    #pragma unroll
                    for (int mi = 0; mi < 4; ++mi) {
                        mma_f16(facc[mi][2 * t + 0], af[mi][ks], bv.x, bv.y);
                        mma_f16(facc[mi][2 * t + 1], af[mi][ks], bv.z, bv.w);
                    }
                }
            }
            if (kc < 14) stage_copyF((kc + 2) % 3, nc, kc + 2);
        }
        __syncthreads();
        if (nc < 3) { stage_copyF(0, nc + 1, 0); stage_copyF(1, nc + 1, 1); }

        #pragma unroll
        for (int mi = 0; mi < 4; ++mi) {
            #pragma unroll
            for (int ni = 0; ni < 4; ++ni) {
                const int col = nc * 128 + nw * 32 + ni * 8 + 2 * (lane & 3);
                const float b0 = bias_s[col], b1 = bias_s[col + 1];
                #pragma unroll
                for (int e = 0; e < 2; ++e) {
                    const int row = mw * 64 + mi * 16 + e * 8 + (lane >> 2);
                    float v0 = fmaxf(facc[mi][ni][2 * e + 0] + b0, 0.0f);
                    float v1 = fmaxf(facc[mi][ni][2 * e + 1] + b1, 0.0f);
                    *(__half2*)(g_Rh + (tok0 + row) * 512 + col) =
                        __floats2half2_rn(v0, v1);
                }
            }
        }
    }
}

// ---------------- scatter: out[t,:] = f32(Rh[slot[ids[t]],:]) ----------------
__global__ void __launch_bounds__(256) scatter_out(const int* __restrict__ ids,
                                                   float* __restrict__ out) {
    size_t i = (size_t)blockIdx.x * 256 + threadIdx.x;   // NTOK*128 threads
    int token = (int)(i >> 7);
    int c4 = (int)(i & 127);
    int slot = g_slot[ids[token]];
    uint2 u = *(const uint2*)(g_Rh + (size_t)slot * 512 + c4 * 4);
    __half2 h0 = *(__half2*)&u.x;
    __half2 h1 = *(__half2*)&u.y;
    float2 f0 = __half22float2(h0);
    float2 f1 = __half22float2(h1);
    __stcs(((float4*)out) + i, make_float4(f0.x, f0.y, f1.x, f1.y));
}

// ---------------- launch ----------------
extern "C" void kernel_launch(void* const* d_in, const int* in_sizes, int n_in,
                              void* d_out, int out_size) {
    (void)in_sizes; (void)n_in; (void)out_size;
    const int*   ids  = (const int*)d_in[0];
    const float* emb  = (const float*)d_in[1];
    const float* Wih0 = (const float*)d_in[2];
    const float* bih0 = (const float*)d_in[4];
    const float* bhh0 = (const float*)d_in[5];
    const float* Wih1 = (const float*)d_in[6];
    const float* bih1 = (const float*)d_in[8];
    const float* bhh1 = (const float*)d_in[9];
    const float* Wlin = (const float*)d_in[10];
    const float* blin = (const float*)d_in[11];
    float* out = (float*)d_out;

    cudaFuncSetAttribute(fused_gemm,
                         cudaFuncAttributeMaxDynamicSharedMemorySize, L_SMEM);

    f2h_all<<<(589824 + 255) / 256, 256>>>(Wih0, Wih1, Wlin);   // + dedup reset
    mark_k<<<NTOK / 256, 256>>>(ids);
    compact_k<<<(VOCABP + 255) / 256, 256>>>();
    emb_gather<<<(VOCABP * 64) / 256, 256>>>(emb);
    fused_gemm<<<NVT, THREADS, L_SMEM>>>(bih0, bhh0, bih1, bhh1, blin);
    scatter_out<<<(NTOK * 128) / 256, 256>>>(ids, out);
}